// round 14
// baseline (speedup 1.0000x reference)
#include <cuda_runtime.h>
#include <cuda_bf16.h>
#include <cstdint>

#define N_NODES 100000
#define F_DIM   64
#define N_EDGES 1000000
#define ALPHA   0.1f
#define BETA    0.5f
#define CAP     64

#define A_STRIDE 36                    // smem row stride in uint32 (144B)
#define NCHUNK   4

// Scratch (__device__ globals; cudaMalloc forbidden)
__device__ int                 g_cnt[N_NODES];
__device__ unsigned long long  g_bucket[(size_t)N_NODES * CAP];   // (val<<32)|src
// support as packed bf16 planes: word j of row = REAL cols (j, j+32)
__device__ uint32_t            g_Ahi2[(size_t)N_NODES * 32];      // 12.8 MB
__device__ uint32_t            g_Alo2[(size_t)N_NODES * 32];      // 12.8 MB
// B fragments: [(kchunk*8+nb)*2+hl] -> 32 lanes x {b0,b1}, logical-k permuted
__device__ uint2               g_Bf[64 * 32];                     // 16 KB

// logical k (GEMM reduction index) -> real feature column
__host__ __device__ __forceinline__ int kperm(int k) {
    return (k & 1) ? (k >> 1) + 32 : (k >> 1);
}

// ---------------------------------------------------------------------------
// K0a: zero counters (critical path, tiny)
// ---------------------------------------------------------------------------
__global__ void zero_kernel() {
    int i = blockIdx.x * blockDim.x + threadIdx.x;
    if (i < N_NODES / 4)
        reinterpret_cast<int4*>(g_cnt)[i] = make_int4(0, 0, 0, 0);
}

// ---------------------------------------------------------------------------
// K0b: W' B-fragments (bf16 hi/lo, k-permuted) — runs on side stream,
//      overlapped with fill/gather.
// ---------------------------------------------------------------------------
__device__ __forceinline__ float wprime(const float* W, int k, int n) {
    return BETA * W[k * 64 + n] + ((k == n) ? (1.0f - BETA) : 0.0f);
}
__global__ void prepB_kernel(const float* __restrict__ W) {
    int i = blockIdx.x * blockDim.x + threadIdx.x;
    if (i < 1024) {                       // (c, nb, lane)
        int c    = i >> 8;
        int nb   = (i >> 5) & 7;
        int lane = i & 31;
        int n  = nb * 8 + (lane >> 2);
        int k0 = c * 16 + (lane & 3) * 2;
        float v[4] = { wprime(W, kperm(k0),     n), wprime(W, kperm(k0 + 1), n),
                       wprime(W, kperm(k0 + 8), n), wprime(W, kperm(k0 + 9), n) };
        uint32_t hp[2], lp[2];
        #pragma unroll
        for (int r = 0; r < 2; r++) {
            __nv_bfloat16 h0 = __float2bfloat16(v[r*2+0]);
            __nv_bfloat16 h1 = __float2bfloat16(v[r*2+1]);
            __nv_bfloat16 l0 = __float2bfloat16(v[r*2+0] - __bfloat162float(h0));
            __nv_bfloat16 l1 = __float2bfloat16(v[r*2+1] - __bfloat162float(h1));
            hp[r] = ((uint32_t)__bfloat16_as_ushort(h1) << 16) | __bfloat16_as_ushort(h0);
            lp[r] = ((uint32_t)__bfloat16_as_ushort(l1) << 16) | __bfloat16_as_ushort(l0);
        }
        int base = (c * 8 + nb) * 2;
        g_Bf[(base + 0) * 32 + lane] = make_uint2(hp[0], hp[1]);
        g_Bf[(base + 1) * 32 + lane] = make_uint2(lp[0], lp[1]);
    }
}

// ---------------------------------------------------------------------------
// K1: bucket fill — scalar, int atomics
// ---------------------------------------------------------------------------
__global__ void fill_kernel(const int*   __restrict__ src,
                            const int*   __restrict__ dst,
                            const float* __restrict__ val) {
    int e = blockIdx.x * blockDim.x + threadIdx.x;
    if (e >= N_EDGES) return;
    int d = dst[e];
    int pos = atomicAdd(&g_cnt[d], 1);
    if (pos < CAP) {
        unsigned long long p =
            ((unsigned long long)__float_as_uint((1.0f - ALPHA) * val[e]) << 32)
            | (unsigned int)src[e];
        g_bucket[(size_t)d * CAP + pos] = p;
    }
}

// ---------------------------------------------------------------------------
// K2: gather — one warp per node (round-12 body, chunked via node_base/n).
// ---------------------------------------------------------------------------
__global__ void __launch_bounds__(256) gather_kernel(const float* __restrict__ feat,
                                                     const float* __restrict__ f0,
                                                     int node_base, int n_nodes) {
    int w = (blockIdx.x * blockDim.x + threadIdx.x) >> 5;
    int lane = threadIdx.x & 31;
    if (w >= n_nodes) return;
    int node = node_base + w;

    size_t row = (size_t)node * F_DIM;
    float a0 = ALPHA * __ldg(&f0[row + lane]);
    float a1 = ALPHA * __ldg(&f0[row + 32 + lane]);

    int cnt = min(g_cnt[node], CAP);
    const unsigned long long* bk = &g_bucket[(size_t)node * CAP];

    if (cnt > 0) {
        int c1 = cnt - 1;
        unsigned long long p0 = bk[0];
        unsigned long long p1 = bk[min(1, c1)];
        unsigned long long p2 = bk[min(2, c1)];
        size_t s0 = (size_t)(unsigned)(p0 & 0xffffffffu) * F_DIM;
        size_t s1 = (size_t)(unsigned)(p1 & 0xffffffffu) * F_DIM;
        float f0a = feat[s0 + lane], f0b = feat[s0 + 32 + lane];
        float f1a = feat[s1 + lane], f1b = feat[s1 + 32 + lane];

        for (int e = 0; e < cnt; e++) {
            unsigned long long p3 = bk[min(e + 3, c1)];
            size_t s2 = (size_t)(unsigned)(p2 & 0xffffffffu) * F_DIM;
            float f2a = feat[s2 + lane];
            float f2b = feat[s2 + 32 + lane];

            float w0 = __uint_as_float((unsigned)(p0 >> 32));
            a0 = fmaf(w0, f0a, a0);
            a1 = fmaf(w0, f0b, a1);

            p0 = p1; p1 = p2; p2 = p3;
            f0a = f1a; f0b = f1b;
            f1a = f2a; f1b = f2b;
        }
    }

    __nv_bfloat16 hx = __float2bfloat16(a0);
    __nv_bfloat16 hy = __float2bfloat16(a1);
    __nv_bfloat16 lx = __float2bfloat16(a0 - __bfloat162float(hx));
    __nv_bfloat16 ly = __float2bfloat16(a1 - __bfloat162float(hy));
    uint32_t hp = ((uint32_t)__bfloat16_as_ushort(hy) << 16) | __bfloat16_as_ushort(hx);
    uint32_t lp = ((uint32_t)__bfloat16_as_ushort(ly) << 16) | __bfloat16_as_ushort(lx);
    g_Ahi2[(size_t)node * 32 + lane] = hp;
    g_Alo2[(size_t)node * 32 + lane] = lp;
}

// ---------------------------------------------------------------------------
// K3: GEMM via mma.sync m16n8k16 bf16, 3-term split, + ReLU (round-12 body,
//     chunked via block_base).
// ---------------------------------------------------------------------------
__device__ __forceinline__ void mma16816(float& d0, float& d1, float& d2, float& d3,
                                         uint32_t a0, uint32_t a1, uint32_t a2, uint32_t a3,
                                         uint2 b) {
    asm volatile(
        "mma.sync.aligned.m16n8k16.row.col.f32.bf16.bf16.f32 "
        "{%0,%1,%2,%3}, {%4,%5,%6,%7}, {%8,%9}, {%0,%1,%2,%3};"
        : "+f"(d0), "+f"(d1), "+f"(d2), "+f"(d3)
        : "r"(a0), "r"(a1), "r"(a2), "r"(a3), "r"(b.x), "r"(b.y));
}

__global__ void __launch_bounds__(128) mma_kernel(float* __restrict__ out,
                                                  int block_base) {
    __shared__ uint32_t sh[2][128 * A_STRIDE];   // 36.9 KB

    int tid  = threadIdx.x, wid = tid >> 5, lane = tid & 31;
    int base = (block_base + blockIdx.x) * 128;

    #pragma unroll
    for (int p = 0; p < 2; p++) {
        const uint4* src = reinterpret_cast<const uint4*>(p ? g_Alo2 : g_Ahi2);
        #pragma unroll
        for (int i = 0; i < 8; i++) {
            int u   = tid + i * 128;       // 0..1023
            int row = u >> 3, w4 = u & 7;
            int node = base + row;
            uint4 v = (node < N_NODES) ? __ldg(&src[(size_t)node * 8 + w4])
                                       : make_uint4(0, 0, 0, 0);
            *reinterpret_cast<uint4*>(&sh[p][row * A_STRIDE + w4 * 4]) = v;
        }
    }
    __syncthreads();

    int lrow   = (lane & 7) + ((lane >> 3) & 1) * 8;
    int colsel = (lane >> 4) * 4;
    uint32_t ah[2][4][4], al[2][4][4];
    #pragma unroll
    for (int t = 0; t < 2; t++) {
        int row_l = wid * 32 + t * 16 + lrow;
        #pragma unroll
        for (int c = 0; c < 4; c++) {
            uint32_t addr_h = (uint32_t)__cvta_generic_to_shared(
                &sh[0][row_l * A_STRIDE + c * 8 + colsel]);
            uint32_t addr_l = (uint32_t)__cvta_generic_to_shared(
                &sh[1][row_l * A_STRIDE + c * 8 + colsel]);
            asm volatile("ldmatrix.sync.aligned.m8n8.x4.shared.b16 {%0,%1,%2,%3}, [%4];"
                : "=r"(ah[t][c][0]), "=r"(ah[t][c][1]), "=r"(ah[t][c][2]), "=r"(ah[t][c][3])
                : "r"(addr_h));
            asm volatile("ldmatrix.sync.aligned.m8n8.x4.shared.b16 {%0,%1,%2,%3}, [%4];"
                : "=r"(al[t][c][0]), "=r"(al[t][c][1]), "=r"(al[t][c][2]), "=r"(al[t][c][3])
                : "r"(addr_l));
        }
    }

    int grp = lane >> 2, qp = lane & 3;

    #pragma unroll
    for (int nb = 0; nb < 8; nb++) {
        float d[2][4];
        #pragma unroll
        for (int t = 0; t < 2; t++)
            d[t][0] = d[t][1] = d[t][2] = d[t][3] = 0.f;

        #pragma unroll
        for (int c = 0; c < 4; c++) {
            int bbase = (c * 8 + nb) * 2;
            uint2 bh = __ldg(&g_Bf[(bbase + 0) * 32 + lane]);
            uint2 bl = __ldg(&g_Bf[(bbase + 1) * 32 + lane]);
            #pragma unroll
            for (int t = 0; t < 2; t++) {
                mma16816(d[t][0], d[t][1], d[t][2], d[t][3],
                         ah[t][c][0], ah[t][c][1], ah[t][c][2], ah[t][c][3], bh);
                mma16816(d[t][0], d[t][1], d[t][2], d[t][3],
                         ah[t][c][0], ah[t][c][1], ah[t][c][2], ah[t][c][3], bl);
                mma16816(d[t][0], d[t][1], d[t][2], d[t][3],
                         al[t][c][0], al[t][c][1], al[t][c][2], al[t][c][3], bh);
            }
        }
        int col = nb * 8 + qp * 2;
        #pragma unroll
        for (int t = 0; t < 2; t++) {
            int row0 = base + wid * 32 + t * 16 + grp;
            if (row0 < N_NODES)
                *reinterpret_cast<float2*>(&out[(size_t)row0 * F_DIM + col]) =
                    make_float2(fmaxf(d[t][0], 0.f), fmaxf(d[t][1], 0.f));
            if (row0 + 8 < N_NODES)
                *reinterpret_cast<float2*>(&out[(size_t)(row0 + 8) * F_DIM + col]) =
                    make_float2(fmaxf(d[t][2], 0.f), fmaxf(d[t][3], 0.f));
        }
    }
}

// ---------------------------------------------------------------------------
// Launch: fork/join pipeline. Main stream: zero -> fill -> gather chunks.
// Side stream: prepB, then mma chunk i after gather chunk i completes.
// Chunk boundaries are multiples of 128 nodes.
// inputs: 0=features, 1=features0, 2=edge_src, 3=edge_dst, 4=edge_vals, 5=W
// ---------------------------------------------------------------------------
extern "C" void kernel_launch(void* const* d_in, const int* in_sizes, int n_in,
                              void* d_out, int out_size) {
    const float* features  = (const float*)d_in[0];
    const float* features0 = (const float*)d_in[1];
    const int*   edge_src  = (const int*)d_in[2];
    const int*   edge_dst  = (const int*)d_in[3];
    const float* edge_vals = (const float*)d_in[4];
    const float* W         = (const float*)d_in[5];
    float* out = (float*)d_out;

    static cudaStream_t s1 = nullptr;
    static cudaEvent_t  eFork, eG[NCHUNK], eDone;
    if (s1 == nullptr) {
        cudaStreamCreateWithFlags(&s1, cudaStreamNonBlocking);
        cudaEventCreateWithFlags(&eFork, cudaEventDisableTiming);
        for (int i = 0; i < NCHUNK; i++)
            cudaEventCreateWithFlags(&eG[i], cudaEventDisableTiming);
        cudaEventCreateWithFlags(&eDone, cudaEventDisableTiming);
    }

    // node chunks (multiples of 128): 3 x 25600 + 23200
    const int chunk_nodes[NCHUNK]  = {25600, 25600, 25600, 23200};
    const int chunk_base[NCHUNK]   = {0, 25600, 51200, 76800};
    const int chunk_blocks[NCHUNK] = {200, 200, 200, 182};   // 128-node tiles

    // main stream: zero counters, fork side stream
    zero_kernel<<<(N_NODES / 4 + 255) / 256, 256>>>();
    cudaEventRecord(eFork, 0);
    cudaStreamWaitEvent(s1, eFork, 0);

    // side stream: B fragments (overlaps fill/gather)
    prepB_kernel<<<4, 256, 0, s1>>>(W);

    // main stream: fill
    fill_kernel<<<(N_EDGES + 255) / 256, 256>>>(edge_src, edge_dst, edge_vals);

    // pipeline: gather chunk on main, mma chunk on side
    for (int c = 0; c < NCHUNK; c++) {
        int gblocks = (chunk_nodes[c] * 32 + 255) / 256;
        gather_kernel<<<gblocks, 256>>>(features, features0,
                                        chunk_base[c], chunk_nodes[c]);
        cudaEventRecord(eG[c], 0);
        cudaStreamWaitEvent(s1, eG[c], 0);
        mma_kernel<<<chunk_blocks[c], 128, 0, s1>>>(out, chunk_base[c] / 128);
    }

    // join
    cudaEventRecord(eDone, s1);
    cudaStreamWaitEvent(0, eDone, 0);
}

// round 15
// speedup vs baseline: 1.0113x; 1.0113x over previous
#include <cuda_runtime.h>
#include <cuda_bf16.h>
#include <cuda_fp16.h>
#include <cstdint>

#define N_NODES 100000
#define F_DIM   64
#define N_EDGES 1000000
#define ALPHA   0.1f
#define BETA    0.5f
#define CAP     64

#define A_STRIDE 36                    // smem row stride in uint32 (144B)

// Scratch (__device__ globals; cudaMalloc forbidden)
__device__ int                 g_cnt[N_NODES];
__device__ unsigned long long  g_bucket[(size_t)N_NODES * CAP];   // (val<<32)|src
__device__ __half2             g_feat16[(size_t)N_NODES * 32];    // 12.8 MB fp16 features
// support as packed bf16 planes: word j of node row = cols (2j, 2j+1)
__device__ uint32_t            g_Ahi2[(size_t)N_NODES * 32];      // 12.8 MB
__device__ uint32_t            g_Alo2[(size_t)N_NODES * 32];      // 12.8 MB
// B fragments: [(kchunk*8+nb)*2+hl] -> 32 lanes x {b0,b1}; identity k
__device__ uint2               g_Bf[64 * 32];                     // 16 KB

// ---------------------------------------------------------------------------
// K0: zero counters + W' B-fragments (bf16 hi/lo, identity k — matches plane
//     layout word j = cols (2j, 2j+1)). Round-13 version (validated).
// ---------------------------------------------------------------------------
__device__ __forceinline__ float wprime(const float* W, int k, int n) {
    return BETA * W[k * 64 + n] + ((k == n) ? (1.0f - BETA) : 0.0f);
}
__global__ void prep_kernel(const float* __restrict__ W) {
    int i = blockIdx.x * blockDim.x + threadIdx.x;
    if (i < N_NODES / 4)
        reinterpret_cast<int4*>(g_cnt)[i] = make_int4(0, 0, 0, 0);
    if (i < 1024) {                       // (c, nb, lane)
        int c    = i >> 8;
        int nb   = (i >> 5) & 7;
        int lane = i & 31;
        int n  = nb * 8 + (lane >> 2);
        int k0 = c * 16 + (lane & 3) * 2;
        float v[4] = { wprime(W, k0,     n), wprime(W, k0 + 1, n),
                       wprime(W, k0 + 8, n), wprime(W, k0 + 9, n) };
        uint32_t hp[2], lp[2];
        #pragma unroll
        for (int r = 0; r < 2; r++) {
            __nv_bfloat16 h0 = __float2bfloat16(v[r*2+0]);
            __nv_bfloat16 h1 = __float2bfloat16(v[r*2+1]);
            __nv_bfloat16 l0 = __float2bfloat16(v[r*2+0] - __bfloat162float(h0));
            __nv_bfloat16 l1 = __float2bfloat16(v[r*2+1] - __bfloat162float(h1));
            hp[r] = ((uint32_t)__bfloat16_as_ushort(h1) << 16) | __bfloat16_as_ushort(h0);
            lp[r] = ((uint32_t)__bfloat16_as_ushort(l1) << 16) | __bfloat16_as_ushort(l0);
        }
        int base = (c * 8 + nb) * 2;
        g_Bf[(base + 0) * 32 + lane] = make_uint2(hp[0], hp[1]);
        g_Bf[(base + 1) * 32 + lane] = make_uint2(lp[0], lp[1]);
    }
}

// ---------------------------------------------------------------------------
// K0b: features fp32 -> fp16 (element pair per thread, coalesced)
// ---------------------------------------------------------------------------
__global__ void convert_kernel(const float2* __restrict__ feat2) {
    int i = blockIdx.x * blockDim.x + threadIdx.x;
    if (i < N_NODES * 32)
        g_feat16[i] = __float22half2_rn(__ldg(&feat2[i]));
}

// ---------------------------------------------------------------------------
// K1: bucket fill — scalar, int atomics
// ---------------------------------------------------------------------------
__global__ void fill_kernel(const int*   __restrict__ src,
                            const int*   __restrict__ dst,
                            const float* __restrict__ val) {
    int e = blockIdx.x * blockDim.x + threadIdx.x;
    if (e >= N_EDGES) return;
    int d = dst[e];
    int pos = atomicAdd(&g_cnt[d], 1);
    if (pos < CAP) {
        unsigned long long p =
            ((unsigned long long)__float_as_uint((1.0f - ALPHA) * val[e]) << 32)
            | (unsigned int)src[e];
        g_bucket[(size_t)d * CAP + pos] = p;
    }
}

// ---------------------------------------------------------------------------
// K2: gather — one warp per node, fp16 feature rows (HALF the bytes).
//     Lane owns cols (2l, 2l+1) = one __half2 = plane word l.
//     Decoupled 3-deep pipeline (round-12 shape). Accumulate fp32.
// ---------------------------------------------------------------------------
__global__ void __launch_bounds__(256) gather_kernel(const float2* __restrict__ f02) {
    int node = (blockIdx.x * blockDim.x + threadIdx.x) >> 5;
    int lane = threadIdx.x & 31;
    if (node >= N_NODES) return;

    float2 fv = __ldg(&f02[(size_t)node * 32 + lane]);
    float a0 = ALPHA * fv.x;
    float a1 = ALPHA * fv.y;

    int cnt = min(g_cnt[node], CAP);
    const unsigned long long* bk = &g_bucket[(size_t)node * CAP];

    if (cnt > 0) {
        int c1 = cnt - 1;
        unsigned long long p0 = bk[0];
        unsigned long long p1 = bk[min(1, c1)];
        unsigned long long p2 = bk[min(2, c1)];
        __half2 h0 = g_feat16[(size_t)(unsigned)(p0 & 0xffffffffu) * 32 + lane];
        __half2 h1 = g_feat16[(size_t)(unsigned)(p1 & 0xffffffffu) * 32 + lane];

        for (int e = 0; e < cnt; e++) {
            unsigned long long p3 = bk[min(e + 3, c1)];
            // feature row for entry e+2 — address ready from last iteration
            __half2 h2 = g_feat16[(size_t)(unsigned)(p2 & 0xffffffffu) * 32 + lane];

            float w = __uint_as_float((unsigned)(p0 >> 32));
            float2 f = __half22float2(h0);
            a0 = fmaf(w, f.x, a0);
            a1 = fmaf(w, f.y, a1);

            p0 = p1; p1 = p2; p2 = p3;
            h0 = h1; h1 = h2;
        }
    }

    // hi/lo bf16 split; low 16 bits = even column (2l)
    __nv_bfloat16 hx = __float2bfloat16(a0);
    __nv_bfloat16 hy = __float2bfloat16(a1);
    __nv_bfloat16 lx = __float2bfloat16(a0 - __bfloat162float(hx));
    __nv_bfloat16 ly = __float2bfloat16(a1 - __bfloat162float(hy));
    uint32_t hp = ((uint32_t)__bfloat16_as_ushort(hy) << 16) | __bfloat16_as_ushort(hx);
    uint32_t lp = ((uint32_t)__bfloat16_as_ushort(ly) << 16) | __bfloat16_as_ushort(lx);
    g_Ahi2[(size_t)node * 32 + lane] = hp;   // word l = cols (2l, 2l+1)
    g_Alo2[(size_t)node * 32 + lane] = lp;
}

// ---------------------------------------------------------------------------
// K3: GEMM via mma.sync m16n8k16 bf16, 3-term split, + ReLU.
// 128 thr / 4 warps, 32 nodes per warp. (round 12/13 body, measured 19.4us)
// ---------------------------------------------------------------------------
__device__ __forceinline__ void mma16816(float& d0, float& d1, float& d2, float& d3,
                                         uint32_t a0, uint32_t a1, uint32_t a2, uint32_t a3,
                                         uint2 b) {
    asm volatile(
        "mma.sync.aligned.m16n8k16.row.col.f32.bf16.bf16.f32 "
        "{%0,%1,%2,%3}, {%4,%5,%6,%7}, {%8,%9}, {%0,%1,%2,%3};"
        : "+f"(d0), "+f"(d1), "+f"(d2), "+f"(d3)
        : "r"(a0), "r"(a1), "r"(a2), "r"(a3), "r"(b.x), "r"(b.y));
}

__global__ void __launch_bounds__(128) mma_kernel(float* __restrict__ out) {
    __shared__ uint32_t sh[2][128 * A_STRIDE];   // 36.9 KB

    int tid  = threadIdx.x, wid = tid >> 5, lane = tid & 31;
    int base = blockIdx.x * 128;

    #pragma unroll
    for (int p = 0; p < 2; p++) {
        const uint4* src = reinterpret_cast<const uint4*>(p ? g_Alo2 : g_Ahi2);
        #pragma unroll
        for (int i = 0; i < 8; i++) {
            int u   = tid + i * 128;       // 0..1023
            int row = u >> 3, w4 = u & 7;
            int node = base + row;
            uint4 v = (node < N_NODES) ? __ldg(&src[(size_t)node * 8 + w4])
                                       : make_uint4(0, 0, 0, 0);
            *reinterpret_cast<uint4*>(&sh[p][row * A_STRIDE + w4 * 4]) = v;
        }
    }
    __syncthreads();

    int lrow   = (lane & 7) + ((lane >> 3) & 1) * 8;
    int colsel = (lane >> 4) * 4;
    uint32_t ah[2][4][4], al[2][4][4];
    #pragma unroll
    for (int t = 0; t < 2; t++) {
        int row_l = wid * 32 + t * 16 + lrow;
        #pragma unroll
        for (int c = 0; c < 4; c++) {
            uint32_t addr_h = (uint32_t)__cvta_generic_to_shared(
                &sh[0][row_l * A_STRIDE + c * 8 + colsel]);
            uint32_t addr_l = (uint32_t)__cvta_generic_to_shared(
                &sh[1][row_l * A_STRIDE + c * 8 + colsel]);
            asm volatile("ldmatrix.sync.aligned.m8n8.x4.shared.b16 {%0,%1,%2,%3}, [%4];"
                : "=r"(ah[t][c][0]), "=r"(ah[t][c][1]), "=r"(ah[t][c][2]), "=r"(ah[t][c][3])
                : "r"(addr_h));
            asm volatile("ldmatrix.sync.aligned.m8n8.x4.shared.b16 {%0,%1,%2,%3}, [%4];"
                : "=r"(al[t][c][0]), "=r"(al[t][c][1]), "=r"(al[t][c][2]), "=r"(al[t][c][3])
                : "r"(addr_l));
        }
    }

    int grp = lane >> 2, qp = lane & 3;

    #pragma unroll
    for (int nb = 0; nb < 8; nb++) {
        float d[2][4];
        #pragma unroll
        for (int t = 0; t < 2; t++)
            d[t][0] = d[t][1] = d[t][2] = d[t][3] = 0.f;

        #pragma unroll
        for (int c = 0; c < 4; c++) {
            int bbase = (c * 8 + nb) * 2;
            uint2 bh = __ldg(&g_Bf[(bbase + 0) * 32 + lane]);
            uint2 bl = __ldg(&g_Bf[(bbase + 1) * 32 + lane]);
            #pragma unroll
            for (int t = 0; t < 2; t++) {
                mma16816(d[t][0], d[t][1], d[t][2], d[t][3],
                         ah[t][c][0], ah[t][c][1], ah[t][c][2], ah[t][c][3], bh);
                mma16816(d[t][0], d[t][1], d[t][2], d[t][3],
                         ah[t][c][0], ah[t][c][1], ah[t][c][2], ah[t][c][3], bl);
                mma16816(d[t][0], d[t][1], d[t][2], d[t][3],
                         al[t][c][0], al[t][c][1], al[t][c][2], al[t][c][3], bh);
            }
        }
        int col = nb * 8 + qp * 2;
        #pragma unroll
        for (int t = 0; t < 2; t++) {
            int row0 = base + wid * 32 + t * 16 + grp;
            if (row0 < N_NODES)
                *reinterpret_cast<float2*>(&out[(size_t)row0 * F_DIM + col]) =
                    make_float2(fmaxf(d[t][0], 0.f), fmaxf(d[t][1], 0.f));
            if (row0 + 8 < N_NODES)
                *reinterpret_cast<float2*>(&out[(size_t)(row0 + 8) * F_DIM + col]) =
                    make_float2(fmaxf(d[t][2], 0.f), fmaxf(d[t][3], 0.f));
        }
    }
}

// ---------------------------------------------------------------------------
// inputs: 0=features, 1=features0, 2=edge_src, 3=edge_dst, 4=edge_vals, 5=W
// ---------------------------------------------------------------------------
extern "C" void kernel_launch(void* const* d_in, const int* in_sizes, int n_in,
                              void* d_out, int out_size) {
    const float* features  = (const float*)d_in[0];
    const float* features0 = (const float*)d_in[1];
    const int*   edge_src  = (const int*)d_in[2];
    const int*   edge_dst  = (const int*)d_in[3];
    const float* edge_vals = (const float*)d_in[4];
    const float* W         = (const float*)d_in[5];
    float* out = (float*)d_out;

    prep_kernel<<<(N_NODES / 4 + 255) / 256, 256>>>(W);
    convert_kernel<<<(N_NODES * 32 + 255) / 256, 256>>>(
        reinterpret_cast<const float2*>(features));
    fill_kernel<<<(N_EDGES + 255) / 256, 256>>>(edge_src, edge_dst, edge_vals);

    long long gthreads = (long long)N_NODES * 32;
    gather_kernel<<<(int)((gthreads + 255) / 256), 256>>>(
        reinterpret_cast<const float2*>(features0));

    mma_kernel<<<(N_NODES + 127) / 128, 128>>>(out);
}

// round 16
// speedup vs baseline: 1.0675x; 1.0556x over previous
#include <cuda_runtime.h>
#include <cuda_bf16.h>
#include <cstdint>

#define N_NODES 100000
#define F_DIM   64
#define N_EDGES 1000000
#define ALPHA   0.1f
#define BETA    0.5f
#define CAP     64

#define A_STRIDE 36                    // smem row stride in uint32 (144B)

// Scratch (__device__ globals; cudaMalloc forbidden)
__device__ int                 g_cnt[N_NODES];
__device__ unsigned long long  g_bucket[(size_t)N_NODES * CAP];   // (val<<32)|src
// support as packed bf16 planes: word j of row = REAL cols (j, j+32)
__device__ uint32_t            g_Ahi2[(size_t)N_NODES * 32];      // 12.8 MB
__device__ uint32_t            g_Alo2[(size_t)N_NODES * 32];      // 12.8 MB
// B fragments: [(kchunk*8+nb)*2+hl] -> 32 lanes x {b0,b1}, logical-k permuted
__device__ uint2               g_Bf[64 * 32];                     // 16 KB

// logical k (GEMM reduction index) -> real feature column
__host__ __device__ __forceinline__ int kperm(int k) {
    return (k & 1) ? (k >> 1) + 32 : (k >> 1);
}

// ---------------------------------------------------------------------------
// K0: zero counters + W' B-fragments (bf16 hi/lo, k-permuted to match the
//     gather's plane layout: word j = cols (j, j+32)).  [round-12, validated]
// ---------------------------------------------------------------------------
__device__ __forceinline__ float wprime(const float* W, int k, int n) {
    return BETA * W[k * 64 + n] + ((k == n) ? (1.0f - BETA) : 0.0f);
}
__global__ void prep_kernel(const float* __restrict__ W) {
    int i = blockIdx.x * blockDim.x + threadIdx.x;
    if (i < N_NODES / 4)
        reinterpret_cast<int4*>(g_cnt)[i] = make_int4(0, 0, 0, 0);
    if (i < 1024) {                       // (c, nb, lane)
        int c    = i >> 8;
        int nb   = (i >> 5) & 7;
        int lane = i & 31;
        int n  = nb * 8 + (lane >> 2);
        int k0 = c * 16 + (lane & 3) * 2;
        float v[4] = { wprime(W, kperm(k0),     n), wprime(W, kperm(k0 + 1), n),
                       wprime(W, kperm(k0 + 8), n), wprime(W, kperm(k0 + 9), n) };
        uint32_t hp[2], lp[2];
        #pragma unroll
        for (int r = 0; r < 2; r++) {
            __nv_bfloat16 h0 = __float2bfloat16(v[r*2+0]);
            __nv_bfloat16 h1 = __float2bfloat16(v[r*2+1]);
            __nv_bfloat16 l0 = __float2bfloat16(v[r*2+0] - __bfloat162float(h0));
            __nv_bfloat16 l1 = __float2bfloat16(v[r*2+1] - __bfloat162float(h1));
            hp[r] = ((uint32_t)__bfloat16_as_ushort(h1) << 16) | __bfloat16_as_ushort(h0);
            lp[r] = ((uint32_t)__bfloat16_as_ushort(l1) << 16) | __bfloat16_as_ushort(l0);
        }
        int base = (c * 8 + nb) * 2;
        g_Bf[(base + 0) * 32 + lane] = make_uint2(hp[0], hp[1]);
        g_Bf[(base + 1) * 32 + lane] = make_uint2(lp[0], lp[1]);
    }
}

// ---------------------------------------------------------------------------
// K1: bucket fill — scalar, int atomics
// ---------------------------------------------------------------------------
__global__ void fill_kernel(const int*   __restrict__ src,
                            const int*   __restrict__ dst,
                            const float* __restrict__ val) {
    int e = blockIdx.x * blockDim.x + threadIdx.x;
    if (e >= N_EDGES) return;
    int d = dst[e];
    int pos = atomicAdd(&g_cnt[d], 1);
    if (pos < CAP) {
        unsigned long long p =
            ((unsigned long long)__float_as_uint((1.0f - ALPHA) * val[e]) << 32)
            | (unsigned int)src[e];
        g_bucket[(size_t)d * CAP + pos] = p;
    }
}

// ---------------------------------------------------------------------------
// K2: gather — one warp per node, ISSUE-OPTIMIZED.
//     Bucket entries live in lane registers (2 coalesced LDG.64 total);
//     per-edge (src, w) comes from SHFL broadcast — no per-edge bucket load,
//     no clamps (stale slots hold valid old src ids or 0 -> safe prefetch).
//     Depth-2 feature pipeline; 32-bit address math.
//     Lane owns cols (lane, lane+32) -> plane word lane.
// ---------------------------------------------------------------------------
__global__ void __launch_bounds__(256) gather_kernel(const float* __restrict__ feat,
                                                     const float* __restrict__ f0) {
    int node = (blockIdx.x * blockDim.x + threadIdx.x) >> 5;
    int lane = threadIdx.x & 31;
    if (node >= N_NODES) return;

    int row = node * F_DIM;                      // <= 6.4M, int-safe
    float a0 = ALPHA * __ldg(&f0[row + lane]);
    float a1 = ALPHA * __ldg(&f0[row + 32 + lane]);

    int cnt = min(g_cnt[node], CAP);
    const uint2* bk2 = reinterpret_cast<const uint2*>(&g_bucket[(size_t)node * CAP]);
    // q.x = src (low word), q.y = weight bits (high word) — little-endian u64
    uint2 q0 = bk2[lane];
    uint2 q1 = bk2[32 + lane];

    if (cnt > 0) {
        // ---- edges [0, min(cnt,32)) from q0 ----
        int n0 = min(cnt, 32);
        unsigned sB = __shfl_sync(0xffffffffu, q0.x, 0);
        float    wA, wB = __uint_as_float(__shfl_sync(0xffffffffu, q0.y, 0));
        float fBa = feat[sB * F_DIM + lane];
        float fBb = feat[sB * F_DIM + 32 + lane];
        unsigned sC = __shfl_sync(0xffffffffu, q0.x, 1);
        float    wC = __uint_as_float(__shfl_sync(0xffffffffu, q0.y, 1));
        float fAa, fAb;

        #pragma unroll 2
        for (int e = 0; e < n0; e++) {
            // stage advance: current=A(from B), next-loaded=B(from C), fetch C
            wA = wB;  fAa = fBa;  fAb = fBb;
            float fCa = feat[sC * F_DIM + lane];
            float fCb = feat[sC * F_DIM + 32 + lane];
            unsigned sD = __shfl_sync(0xffffffffu, q0.x, (e + 2) & 31);
            float    wD = __uint_as_float(__shfl_sync(0xffffffffu, q0.y, (e + 2) & 31));

            a0 = fmaf(wA, fAa, a0);
            a1 = fmaf(wA, fAb, a1);

            wB = wC; fBa = fCa; fBb = fCb;
            sC = sD; wC = wD;
        }

        // ---- edges [32, cnt) from q1 (rare: mean degree ~10) ----
        if (cnt > 32) {
            int n1 = cnt - 32;
            unsigned tB = __shfl_sync(0xffffffffu, q1.x, 0);
            float    twB = __uint_as_float(__shfl_sync(0xffffffffu, q1.y, 0));
            float gBa = feat[tB * F_DIM + lane];
            float gBb = feat[tB * F_DIM + 32 + lane];
            unsigned tC = __shfl_sync(0xffffffffu, q1.x, 1);
            float    twC = __uint_as_float(__shfl_sync(0xffffffffu, q1.y, 1));

            for (int e = 0; e < n1; e++) {
                float twA = twB;
                float gAa = gBa, gAb = gBb;
                float gCa = feat[tC * F_DIM + lane];
                float gCb = feat[tC * F_DIM + 32 + lane];
                unsigned tD = __shfl_sync(0xffffffffu, q1.x, (e + 2) & 31);
                float    twD = __uint_as_float(__shfl_sync(0xffffffffu, q1.y, (e + 2) & 31));

                a0 = fmaf(twA, gAa, a0);
                a1 = fmaf(twA, gAb, a1);

                twB = twC; gBa = gCa; gBb = gCb;
                tC = tD; twC = twD;
            }
        }
    }

    __nv_bfloat16 hx = __float2bfloat16(a0);
    __nv_bfloat16 hy = __float2bfloat16(a1);
    __nv_bfloat16 lx = __float2bfloat16(a0 - __bfloat162float(hx));
    __nv_bfloat16 ly = __float2bfloat16(a1 - __bfloat162float(hy));
    uint32_t hp = ((uint32_t)__bfloat16_as_ushort(hy) << 16) | __bfloat16_as_ushort(hx);
    uint32_t lp = ((uint32_t)__bfloat16_as_ushort(ly) << 16) | __bfloat16_as_ushort(lx);
    g_Ahi2[(size_t)node * 32 + lane] = hp;   // word lane = cols (lane, lane+32)
    g_Alo2[(size_t)node * 32 + lane] = lp;
}

// ---------------------------------------------------------------------------
// K3: GEMM via mma.sync m16n8k16 bf16, 3-term split, + ReLU.
// 128 thr / 4 warps, 32 nodes per warp. (round-12 body, measured 19.4us)
// ---------------------------------------------------------------------------
__device__ __forceinline__ void mma16816(float& d0, float& d1, float& d2, float& d3,
                                         uint32_t a0, uint32_t a1, uint32_t a2, uint32_t a3,
                                         uint2 b) {
    asm volatile(
        "mma.sync.aligned.m16n8k16.row.col.f32.bf16.bf16.f32 "
        "{%0,%1,%2,%3}, {%4,%5,%6,%7}, {%8,%9}, {%0,%1,%2,%3};"
        : "+f"(d0), "+f"(d1), "+f"(d2), "+f"(d3)
        : "r"(a0), "r"(a1), "r"(a2), "r"(a3), "r"(b.x), "r"(b.y));
}

__global__ void __launch_bounds__(128) mma_kernel(float* __restrict__ out) {
    __shared__ uint32_t sh[2][128 * A_STRIDE];   // 36.9 KB

    int tid  = threadIdx.x, wid = tid >> 5, lane = tid & 31;
    int base = blockIdx.x * 128;

    #pragma unroll
    for (int p = 0; p < 2; p++) {
        const uint4* src = reinterpret_cast<const uint4*>(p ? g_Alo2 : g_Ahi2);
        #pragma unroll
        for (int i = 0; i < 8; i++) {
            int u   = tid + i * 128;       // 0..1023
            int row = u >> 3, w4 = u & 7;
            int node = base + row;
            uint4 v = (node < N_NODES) ? __ldg(&src[(size_t)node * 8 + w4])
                                       : make_uint4(0, 0, 0, 0);
            *reinterpret_cast<uint4*>(&sh[p][row * A_STRIDE + w4 * 4]) = v;
        }
    }
    __syncthreads();

    int lrow   = (lane & 7) + ((lane >> 3) & 1) * 8;
    int colsel = (lane >> 4) * 4;
    uint32_t ah[2][4][4], al[2][4][4];
    #pragma unroll
    for (int t = 0; t < 2; t++) {
        int row_l = wid * 32 + t * 16 + lrow;
        #pragma unroll
        for (int c = 0; c < 4; c++) {
            uint32_t addr_h = (uint32_t)__cvta_generic_to_shared(
                &sh[0][row_l * A_STRIDE + c * 8 + colsel]);
            uint32_t addr_l = (uint32_t)__cvta_generic_to_shared(
                &sh[1][row_l * A_STRIDE + c * 8 + colsel]);
            asm volatile("ldmatrix.sync.aligned.m8n8.x4.shared.b16 {%0,%1,%2,%3}, [%4];"
                : "=r"(ah[t][c][0]), "=r"(ah[t][c][1]), "=r"(ah[t][c][2]), "=r"(ah[t][c][3])
                : "r"(addr_h));
            asm volatile("ldmatrix.sync.aligned.m8n8.x4.shared.b16 {%0,%1,%2,%3}, [%4];"
                : "=r"(al[t][c][0]), "=r"(al[t][c][1]), "=r"(al[t][c][2]), "=r"(al[t][c][3])
                : "r"(addr_l));
        }
    }

    int grp = lane >> 2, qp = lane & 3;

    #pragma unroll
    for (int nb = 0; nb < 8; nb++) {
        float d[2][4];
        #pragma unroll
        for (int t = 0; t < 2; t++)
            d[t][0] = d[t][1] = d[t][2] = d[t][3] = 0.f;

        #pragma unroll
        for (int c = 0; c < 4; c++) {
            int bbase = (c * 8 + nb) * 2;
            uint2 bh = __ldg(&g_Bf[(bbase + 0) * 32 + lane]);
            uint2 bl = __ldg(&g_Bf[(bbase + 1) * 32 + lane]);
            #pragma unroll
            for (int t = 0; t < 2; t++) {
                mma16816(d[t][0], d[t][1], d[t][2], d[t][3],
                         ah[t][c][0], ah[t][c][1], ah[t][c][2], ah[t][c][3], bh);
                mma16816(d[t][0], d[t][1], d[t][2], d[t][3],
                         ah[t][c][0], ah[t][c][1], ah[t][c][2], ah[t][c][3], bl);
                mma16816(d[t][0], d[t][1], d[t][2], d[t][3],
                         al[t][c][0], al[t][c][1], al[t][c][2], al[t][c][3], bh);
            }
        }
        int col = nb * 8 + qp * 2;
        #pragma unroll
        for (int t = 0; t < 2; t++) {
            int row0 = base + wid * 32 + t * 16 + grp;
            if (row0 < N_NODES)
                *reinterpret_cast<float2*>(&out[(size_t)row0 * F_DIM + col]) =
                    make_float2(fmaxf(d[t][0], 0.f), fmaxf(d[t][1], 0.f));
            if (row0 + 8 < N_NODES)
                *reinterpret_cast<float2*>(&out[(size_t)(row0 + 8) * F_DIM + col]) =
                    make_float2(fmaxf(d[t][2], 0.f), fmaxf(d[t][3], 0.f));
        }
    }
}

// ---------------------------------------------------------------------------
// inputs: 0=features, 1=features0, 2=edge_src, 3=edge_dst, 4=edge_vals, 5=W
// ---------------------------------------------------------------------------
extern "C" void kernel_launch(void* const* d_in, const int* in_sizes, int n_in,
                              void* d_out, int out_size) {
    const float* features  = (const float*)d_in[0];
    const float* features0 = (const float*)d_in[1];
    const int*   edge_src  = (const int*)d_in[2];
    const int*   edge_dst  = (const int*)d_in[3];
    const float* edge_vals = (const float*)d_in[4];
    const float* W         = (const float*)d_in[5];
    float* out = (float*)d_out;

    prep_kernel<<<(N_NODES / 4 + 255) / 256, 256>>>(W);
    fill_kernel<<<(N_EDGES + 255) / 256, 256>>>(edge_src, edge_dst, edge_vals);

    long long gthreads = (long long)N_NODES * 32;
    gather_kernel<<<(int)((gthreads + 255) / 256), 256>>>(features, features0);

    mma_kernel<<<(N_NODES + 127) / 128, 128>>>(out);
}